// round 4
// baseline (speedup 1.0000x reference)
#include <cuda_runtime.h>

// Problem constants
#define B_    4
#define H_    16
#define N_    8192
#define DE    64
#define SPLIT 16
#define TROWS 64
#define KST   68         // smem row stride (floats)
#define EPSV  1e-10f

#define KV_OFF   ((long long)B_ * H_ * N_ * DE)
#define NORM_OFF (KV_OFF + (long long)B_ * H_ * DE * DE)
#define SMEM_BYTES ((3 * 64 * KST + 64 * 64 + 64) * 4)   // 68864 B -> 3 CTAs/SM

typedef unsigned long long ull;
union F4  { float4 v; float a[4]; ull u[2]; };
union F2  { float2 v; float a[2]; };

// ---- f32x2 packed FMA helpers (Blackwell) ----------------------------------
__device__ __forceinline__ ull rep2(float x) {
    ull r; asm("mov.b64 %0, {%1, %1};" : "=l"(r) : "f"(x)); return r;
}
__device__ __forceinline__ void ffma2(ull& d, ull a, ull b) {
    asm("fma.rn.f32x2 %0, %1, %2, %3;" : "=l"(d) : "l"(a), "l"(b), "l"(d));
}
__device__ __forceinline__ void unpack2(float& lo, float& hi, ull p) {
    asm("mov.b64 {%0, %1}, %2;" : "=f"(lo), "=f"(hi) : "l"(p));
}

__device__ __forceinline__ float elu1(float x) {
    return x > 0.f ? x + 1.f : __expf(x);
}
__device__ __forceinline__ float4 elu4(float4 x) {
    float4 r;
    r.x = elu1(x.x); r.y = elu1(x.y); r.z = elu1(x.z); r.w = elu1(x.w);
    return r;
}

// ---------------------------------------------------------------------------
__global__ void fw_init(const float* __restrict__ pkv,
                        const float* __restrict__ pnorm,
                        float* __restrict__ dout) {
    int i = blockIdx.x * blockDim.x + threadIdx.x;
    if (i < B_ * H_ * DE * DE) dout[KV_OFF + i]   = pkv[i];
    if (i < B_ * H_ * DE)      dout[NORM_OFF + i] = pnorm[i];
}

// ---------------------------------------------------------------------------
// 256 threads. tx = tid&7 -> cols {4tx..4tx+3} U {32+4tx..+3}
//              ty = tid>>3 -> rows {2ty, 2ty+1}
// ---------------------------------------------------------------------------
__global__ __launch_bounds__(256, 3)
void fw_main(const float* __restrict__ keys,
             const float* __restrict__ values,
             const float* __restrict__ queries,
             const float* __restrict__ outin,
             const float* __restrict__ pkv,
             const float* __restrict__ pnorm,
             const float* __restrict__ hg,
             float* __restrict__ dout)
{
    extern __shared__ float sm[];
    float* k_s    = sm;                  // [64][KST]
    float* q_s    = k_s + 64 * KST;      // [64][KST]
    float* v_s    = q_s + 64 * KST;      // [64][KST]  (v' written in C1)
    float* pkv_s  = v_s + 64 * KST;      // [64][64]
    float* norm_s = pkv_s + 64 * 64;     // [64]

    const int tid   = threadIdx.x;
    const int split = blockIdx.x;
    const int bh    = blockIdx.y;
    const int h     = bh & (H_ - 1);

    const float gate  = 1.f / (1.f + __expf(-hg[h]));
    const float gate1 = 1.f - gate;

    // Stage past_kv / past_norm
    {
        const float4* pg = (const float4*)(pkv + (long long)bh * DE * DE);
        for (int i = tid; i < DE * DE / 4; i += 256)
            ((float4*)pkv_s)[i] = pg[i];
        if (tid < DE / 4)
            ((float4*)norm_s)[tid] = ((const float4*)(pnorm + bh * DE))[tid];
    }

    const int tx  = tid & 7;
    const int ty  = tid >> 3;
    const int e0a = tx * 4;
    const int e0b = 32 + tx * 4;
    const int r0  = ty * 2;

    // Cross-tile accumulators: new_kv[d0..d0+1][8 cols], norm sums
    ull acc[8];
    #pragma unroll
    for (int p = 0; p < 8; p++) acc[p] = 0ULL;
    float accn0 = 0.f, accn1 = 0.f;

    const long long baseg = (long long)bh * N_ * DE;
    const int rows_per = N_ / SPLIT;     // 512
    const int row0 = split * rows_per;

    __syncthreads();   // pkv_s / norm_s ready

    #pragma unroll 1
    for (int t0 = 0; t0 < rows_per; t0 += TROWS) {
        // ---------------- Phase A: load k,q; elu; stage -------------------
        #pragma unroll
        for (int it = 0; it < 4; it++) {
            int f = tid + it * 256;        // 0..1023 float4 slots
            int row = f >> 4, c = f & 15, d4 = c * 4;
            long long g = baseg + (long long)(row0 + t0 + row) * DE + d4;
            *(float4*)(k_s + row * KST + d4) = elu4(*(const float4*)(keys + g));
            *(float4*)(q_s + row * KST + d4) = elu4(*(const float4*)(queries + g));
        }
        __syncthreads();

        const float* kr0 = k_s + r0 * KST;
        const float* qr0 = q_s + r0 * KST;

        // ---------------- Pass B1: numer_k + denom_k ----------------------
        {
            ull num[8];
            #pragma unroll
            for (int p = 0; p < 8; p++) num[p] = 0ULL;
            float den0 = 0.f, den1 = 0.f;

            #pragma unroll 4
            for (int dq = 0; dq < DE; dq += 4) {
                F4 ka, kb, nn;
                ka.v = *(const float4*)(kr0 + dq);
                kb.v = *(const float4*)(kr0 + KST + dq);
                nn.v = *(const float4*)(norm_s + dq);
                #pragma unroll
                for (int j = 0; j < 4; j++) {
                    F4 pA, pB;
                    pA.v = *(const float4*)(pkv_s + (dq + j) * DE + e0a);
                    pB.v = *(const float4*)(pkv_s + (dq + j) * DE + e0b);
                    ull k0 = rep2(ka.a[j]), k1 = rep2(kb.a[j]);
                    ffma2(num[0], k0, pA.u[0]); ffma2(num[1], k0, pA.u[1]);
                    ffma2(num[2], k0, pB.u[0]); ffma2(num[3], k0, pB.u[1]);
                    ffma2(num[4], k1, pA.u[0]); ffma2(num[5], k1, pA.u[1]);
                    ffma2(num[6], k1, pB.u[0]); ffma2(num[7], k1, pB.u[1]);
                    den0 = fmaf(ka.a[j], nn.a[j], den0);
                    den1 = fmaf(kb.a[j], nn.a[j], den1);
                }
            }

            // ------------ C1: v' = values - numer_k/denom_k -> v_s --------
            float rk0 = __frcp_rn(fmaxf(den0, EPSV));
            float rk1 = __frcp_rn(fmaxf(den1, EPSV));
            #pragma unroll
            for (int i = 0; i < 2; i++) {
                int row = r0 + i;
                float rk = i ? rk1 : rk0;
                long long g = baseg + (long long)(row0 + t0 + row) * DE;
                F4 vA, vB, nvA, nvB;
                vA.v = *(const float4*)(values + g + e0a);
                vB.v = *(const float4*)(values + g + e0b);
                float n0, n1;
                unpack2(n0, n1, num[i * 4 + 0]);
                nvA.a[0] = vA.a[0] - n0 * rk; nvA.a[1] = vA.a[1] - n1 * rk;
                unpack2(n0, n1, num[i * 4 + 1]);
                nvA.a[2] = vA.a[2] - n0 * rk; nvA.a[3] = vA.a[3] - n1 * rk;
                unpack2(n0, n1, num[i * 4 + 2]);
                nvB.a[0] = vB.a[0] - n0 * rk; nvB.a[1] = vB.a[1] - n1 * rk;
                unpack2(n0, n1, num[i * 4 + 3]);
                nvB.a[2] = vB.a[2] - n0 * rk; nvB.a[3] = vB.a[3] - n1 * rk;
                *(float4*)(v_s + row * KST + e0a) = nvA.v;
                *(float4*)(v_s + row * KST + e0b) = nvB.v;
            }
        }

        // ---------------- Pass B2: numer_q + denom_q ----------------------
        {
            ull num[8];
            #pragma unroll
            for (int p = 0; p < 8; p++) num[p] = 0ULL;
            float den0 = 0.f, den1 = 0.f;

            #pragma unroll 4
            for (int dq = 0; dq < DE; dq += 4) {
                F4 qa, qb, nn;
                qa.v = *(const float4*)(qr0 + dq);
                qb.v = *(const float4*)(qr0 + KST + dq);
                nn.v = *(const float4*)(norm_s + dq);
                #pragma unroll
                for (int j = 0; j < 4; j++) {
                    F4 pA, pB;
                    pA.v = *(const float4*)(pkv_s + (dq + j) * DE + e0a);
                    pB.v = *(const float4*)(pkv_s + (dq + j) * DE + e0b);
                    ull q0 = rep2(qa.a[j]), q1 = rep2(qb.a[j]);
                    ffma2(num[0], q0, pA.u[0]); ffma2(num[1], q0, pA.u[1]);
                    ffma2(num[2], q0, pB.u[0]); ffma2(num[3], q0, pB.u[1]);
                    ffma2(num[4], q1, pA.u[0]); ffma2(num[5], q1, pA.u[1]);
                    ffma2(num[6], q1, pB.u[0]); ffma2(num[7], q1, pB.u[1]);
                    den0 = fmaf(qa.a[j], nn.a[j], den0);
                    den1 = fmaf(qb.a[j], nn.a[j], den1);
                }
            }

            // ------------ C2: out_g -> global -----------------------------
            float rq0 = __frcp_rn(fmaxf(den0, EPSV));
            float rq1 = __frcp_rn(fmaxf(den1, EPSV));
            #pragma unroll
            for (int i = 0; i < 2; i++) {
                int row = r0 + i;
                float rq = i ? rq1 : rq0;
                long long g = baseg + (long long)(row0 + t0 + row) * DE;
                F4 oA, oB, gA, gB;
                oA.v = *(const float4*)(outin + g + e0a);
                oB.v = *(const float4*)(outin + g + e0b);
                float n0, n1;
                unpack2(n0, n1, num[i * 4 + 0]);
                gA.a[0] = oA.a[0] * gate + (n0 * rq) * gate1;
                gA.a[1] = oA.a[1] * gate + (n1 * rq) * gate1;
                unpack2(n0, n1, num[i * 4 + 1]);
                gA.a[2] = oA.a[2] * gate + (n0 * rq) * gate1;
                gA.a[3] = oA.a[3] * gate + (n1 * rq) * gate1;
                unpack2(n0, n1, num[i * 4 + 2]);
                gB.a[0] = oB.a[0] * gate + (n0 * rq) * gate1;
                gB.a[1] = oB.a[1] * gate + (n1 * rq) * gate1;
                unpack2(n0, n1, num[i * 4 + 3]);
                gB.a[2] = oB.a[2] * gate + (n0 * rq) * gate1;
                gB.a[3] = oB.a[3] * gate + (n1 * rq) * gate1;
                *(float4*)(dout + g + e0a) = gA.v;
                *(float4*)(dout + g + e0b) = gB.v;
            }
        }
        __syncthreads();   // v_s complete for all rows

        // ---------------- Phase D: new_kv += k^T v' (FFMA2) ---------------
        #pragma unroll 4
        for (int r = 0; r < TROWS; r++) {
            const float* krow = k_s + r * KST;
            const float* vrow = v_s + r * KST;
            F2 kp; kp.v = *(const float2*)(krow + r0);
            F4 vA, vB;
            vA.v = *(const float4*)(vrow + e0a);
            vB.v = *(const float4*)(vrow + e0b);
            ull k0 = rep2(kp.a[0]), k1 = rep2(kp.a[1]);
            ffma2(acc[0], k0, vA.u[0]); ffma2(acc[1], k0, vA.u[1]);
            ffma2(acc[2], k0, vB.u[0]); ffma2(acc[3], k0, vB.u[1]);
            ffma2(acc[4], k1, vA.u[0]); ffma2(acc[5], k1, vA.u[1]);
            ffma2(acc[6], k1, vB.u[0]); ffma2(acc[7], k1, vB.u[1]);
            if (tx == 0) { accn0 += kp.a[0]; accn1 += kp.a[1]; }
        }
        __syncthreads();
    }

    // ---- Epilogue: merge partial new_kv / new_norm -------------------------
    float* kvo = dout + KV_OFF + (long long)bh * DE * DE;
    #pragma unroll
    for (int i = 0; i < 2; i++) {
        float lo, hi;
        unpack2(lo, hi, acc[i * 4 + 0]);
        atomicAdd(&kvo[(r0 + i) * DE + e0a + 0], lo);
        atomicAdd(&kvo[(r0 + i) * DE + e0a + 1], hi);
        unpack2(lo, hi, acc[i * 4 + 1]);
        atomicAdd(&kvo[(r0 + i) * DE + e0a + 2], lo);
        atomicAdd(&kvo[(r0 + i) * DE + e0a + 3], hi);
        unpack2(lo, hi, acc[i * 4 + 2]);
        atomicAdd(&kvo[(r0 + i) * DE + e0b + 0], lo);
        atomicAdd(&kvo[(r0 + i) * DE + e0b + 1], hi);
        unpack2(lo, hi, acc[i * 4 + 3]);
        atomicAdd(&kvo[(r0 + i) * DE + e0b + 2], lo);
        atomicAdd(&kvo[(r0 + i) * DE + e0b + 3], hi);
    }
    if (tx == 0) {
        float* no = dout + NORM_OFF + (long long)bh * DE;
        atomicAdd(&no[r0], accn0);
        atomicAdd(&no[r0 + 1], accn1);
    }
}

// ---------------------------------------------------------------------------
extern "C" void kernel_launch(void* const* d_in, const int* in_sizes, int n_in,
                              void* d_out, int out_size) {
    const float* keys    = (const float*)d_in[0];
    const float* values  = (const float*)d_in[1];
    const float* queries = (const float*)d_in[2];
    const float* outin   = (const float*)d_in[3];
    const float* pkv     = (const float*)d_in[4];
    const float* pnorm   = (const float*)d_in[5];
    const float* hg      = (const float*)d_in[6];
    float* dout = (float*)d_out;

    cudaFuncSetAttribute(fw_main, cudaFuncAttributeMaxDynamicSharedMemorySize,
                         SMEM_BYTES);

    fw_init<<<(B_ * H_ * DE * DE + 255) / 256, 256>>>(pkv, pnorm, dout);

    dim3 grid(SPLIT, B_ * H_);
    fw_main<<<grid, 256, SMEM_BYTES>>>(keys, values, queries, outin,
                                       pkv, pnorm, hg, dout);
}

// round 5
// speedup vs baseline: 1.7877x; 1.7877x over previous
#include <cuda_runtime.h>
#include <cuda_bf16.h>
#include <cstdint>

// Problem constants
#define B_    4
#define H_    16
#define N_    8192
#define DE    64
#define SPLIT 8
#define TM    128
#define EPSV  1e-10f

#define KV_OFF   ((long long)B_ * H_ * N_ * DE)
#define NORM_OFF (KV_OFF + (long long)B_ * H_ * DE * DE)

// bf16 tiles, row stride 72 elements (144 B, 16B-aligned for ldmatrix,
// 4-bank row stagger -> conflict-free ldmatrix and fragment stores)
#define LDB   72
#define LDBB  144
#define SM_KHI 0
#define SM_KLO 18432
#define SM_QHI 36864
#define SM_VHI 55296
#define SM_VLO 73728
#define SM_PHI 92160                 // pkv hi [64][72] (col 64 = norm)
#define SM_PLO (SM_PHI + 9216)
#define SMEM_TOTAL (SM_PLO + 9216)   // 110592 B -> 2 CTAs/SM

union F4 { float4 v; float a[4]; };

// ---------------------------------------------------------------------------
__device__ __forceinline__ uint32_t smem_u32(const void* p) {
    uint32_t a;
    asm("{ .reg .u64 t; cvta.to.shared.u64 t, %1; cvt.u32.u64 %0, t; }"
        : "=r"(a) : "l"(p));
    return a;
}
__device__ __forceinline__ void ldsm4(uint32_t* r, uint32_t addr) {
    asm volatile("ldmatrix.sync.aligned.m8n8.x4.shared.b16 {%0,%1,%2,%3}, [%4];"
        : "=r"(r[0]), "=r"(r[1]), "=r"(r[2]), "=r"(r[3]) : "r"(addr));
}
__device__ __forceinline__ void ldsm4t(uint32_t* r, uint32_t addr) {
    asm volatile("ldmatrix.sync.aligned.m8n8.x4.trans.shared.b16 {%0,%1,%2,%3}, [%4];"
        : "=r"(r[0]), "=r"(r[1]), "=r"(r[2]), "=r"(r[3]) : "r"(addr));
}
__device__ __forceinline__ void ldsm2t(uint32_t* r, uint32_t addr) {
    asm volatile("ldmatrix.sync.aligned.m8n8.x2.trans.shared.b16 {%0,%1}, [%2];"
        : "=r"(r[0]), "=r"(r[1]) : "r"(addr));
}
__device__ __forceinline__ void mma16816(float* c, const uint32_t* a, const uint32_t* b) {
    asm volatile(
        "mma.sync.aligned.m16n8k16.row.col.f32.bf16.bf16.f32 "
        "{%0,%1,%2,%3}, {%4,%5,%6,%7}, {%8,%9}, {%0,%1,%2,%3};"
        : "+f"(c[0]), "+f"(c[1]), "+f"(c[2]), "+f"(c[3])
        : "r"(a[0]), "r"(a[1]), "r"(a[2]), "r"(a[3]), "r"(b[0]), "r"(b[1]));
}

__device__ __forceinline__ float elu1(float x) {
    return x > 0.f ? x + 1.f : __expf(x);
}
__device__ __forceinline__ unsigned packbf(float x, float y) {
    __nv_bfloat162 t(__float2bfloat16(x), __float2bfloat16(y));
    return *reinterpret_cast<unsigned*>(&t);
}
__device__ __forceinline__ void splitf(float x, float& hi, float& lo) {
    hi = __bfloat162float(__float2bfloat16(x));
    lo = x - hi;
}

// ---------------------------------------------------------------------------
__global__ void fw_init(const float* __restrict__ pkv,
                        const float* __restrict__ pnorm,
                        float* __restrict__ dout) {
    int i = blockIdx.x * blockDim.x + threadIdx.x;
    if (i < B_ * H_ * DE * DE) dout[KV_OFF + i]   = pkv[i];
    if (i < B_ * H_ * DE)      dout[NORM_OFF + i] = pnorm[i];
}

// ---------------------------------------------------------------------------
__global__ __launch_bounds__(256, 2)
void fw_main(const float* __restrict__ keys,
             const float* __restrict__ values,
             const float* __restrict__ queries,
             const float* __restrict__ outin,
             const float* __restrict__ pkv,
             const float* __restrict__ pnorm,
             const float* __restrict__ hg,
             float* __restrict__ dout)
{
    extern __shared__ char smc[];
    const uint32_t sb = smem_u32(smc);

    const int tid  = threadIdx.x;
    const int lane = tid & 31;
    const int w    = tid >> 5;          // warp 0..7
    const int R0   = w * 16;            // this warp's row slice in the tile
    const int split = blockIdx.x;
    const int bh    = blockIdx.y;
    const int h     = bh & (H_ - 1);

    const float gate  = 1.f / (1.f + __expf(-hg[h]));
    const float gate1 = 1.f - gate;

    // ---- stage pkv (hi/lo bf16, [d][e], row-major, LDB stride) -------------
    {
        const float* pg = pkv + (long long)bh * DE * DE;
        for (int i = tid; i < DE * DE; i += 256) {
            int d = i >> 6, e = i & 63;
            float hi, lo; splitf(pg[i], hi, lo);
            *(__nv_bfloat16*)(smc + SM_PHI + d * LDBB + e * 2) = __float2bfloat16(hi);
            *(__nv_bfloat16*)(smc + SM_PLO + d * LDBB + e * 2) = __float2bfloat16(lo);
        }
        // column 64 = past_norm (denominator rides in the MMA); 65-71 zero
        const float* pn = pnorm + bh * DE;
        for (int i = tid; i < DE * 8; i += 256) {
            int d = i >> 3, c = 64 + (i & 7);
            float hi = 0.f, lo = 0.f;
            if (c == 64) splitf(pn[d], hi, lo);
            *(__nv_bfloat16*)(smc + SM_PHI + d * LDBB + c * 2) = __float2bfloat16(hi);
            *(__nv_bfloat16*)(smc + SM_PLO + d * LDBB + c * 2) = __float2bfloat16(lo);
        }
    }

    // ldmatrix per-lane address offsets
    const uint32_t aoff  = (uint32_t)(lane & 15) * LDBB + ((lane & 16) ? 16 : 0);
    const uint32_t atoff = (uint32_t)((lane & 7) + ((lane & 16) ? 8 : 0)) * LDBB
                         + ((lane & 8) ? 16 : 0);
    const uint32_t btoff = (uint32_t)(lane & 15) * LDBB;

    const int g8  = lane >> 2;          // fragment row within 8
    const int tig = lane & 3;           // fragment col pair
    const int srcl = (lane >> 2) << 2;  // lane holding this row's denom

    // GEMM2 split: warps 0-3 / 4-7 share d-rows, cover e 0-31 / 32-63
    const int dR   = (w & 3) * 16;
    const int eoff = (w >> 2) * 32;

    float acc2[4][4];                   // new_kv partials [4 nblocks][frag]
    #pragma unroll
    for (int i = 0; i < 4; i++)
        #pragma unroll
        for (int j = 0; j < 4; j++) acc2[i][j] = 0.f;
    float accn[4] = {0.f, 0.f, 0.f, 0.f};

    const long long baseg = (long long)bh * N_ * DE;
    const int rows_per = N_ / SPLIT;    // 1024
    const int row0 = split * rows_per;
    const int c15 = tid & 15;           // phase-A d-chunk

    for (int t = 0; t < rows_per / TM; t++) {
        const int t0 = t * TM;

        // ============ Phase A: load k,q; elu; bf16-split to smem ============
        #pragma unroll
        for (int it = 0; it < 8; it++) {
            int row = (tid >> 4) + it * 16;
            long long g = baseg + (long long)(row0 + t0 + row) * DE + 4 * c15;
            F4 k4, q4;
            k4.v = *(const float4*)(keys + g);
            q4.v = *(const float4*)(queries + g);
            #pragma unroll
            for (int j = 0; j < 4; j++) { k4.a[j] = elu1(k4.a[j]); q4.a[j] = elu1(q4.a[j]); }
            #pragma unroll
            for (int j = 0; j < 4; j++) accn[j] += k4.a[j];

            float h0,l0,h1,l1,h2,l2,h3,l3;
            splitf(k4.a[0],h0,l0); splitf(k4.a[1],h1,l1);
            splitf(k4.a[2],h2,l2); splitf(k4.a[3],h3,l3);
            uint2 khi = make_uint2(packbf(h0,h1), packbf(h2,h3));
            uint2 klo = make_uint2(packbf(l0,l1), packbf(l2,l3));
            uint2 qhi = make_uint2(packbf(q4.a[0],q4.a[1]), packbf(q4.a[2],q4.a[3]));
            uint32_t off = (uint32_t)row * LDBB + 8 * c15;
            *(uint2*)(smc + SM_KHI + off) = khi;
            *(uint2*)(smc + SM_KLO + off) = klo;
            *(uint2*)(smc + SM_QHI + off) = qhi;
        }
        __syncthreads();

        // ============ GEMM1-k: numer_k (+denom in col 64) ===================
        float numk[8][4];
        #pragma unroll
        for (int i = 0; i < 8; i++)
            #pragma unroll
            for (int j = 0; j < 4; j++) numk[i][j] = 0.f;
        float dk[4] = {0.f, 0.f, 0.f, 0.f};

        #pragma unroll
        for (int ks = 0; ks < 4; ks++) {
            uint32_t ah[4], al[4];
            ldsm4(ah, sb + SM_KHI + (uint32_t)R0 * LDBB + ks * 32 + aoff);
            ldsm4(al, sb + SM_KLO + (uint32_t)R0 * LDBB + ks * 32 + aoff);
            #pragma unroll
            for (int nb = 0; nb < 8; nb++) {
                uint32_t bhv[2], blv[2];
                ldsm2t(bhv, sb + SM_PHI + (uint32_t)(ks * 16) * LDBB + nb * 16 + btoff);
                ldsm2t(blv, sb + SM_PLO + (uint32_t)(ks * 16) * LDBB + nb * 16 + btoff);
                mma16816(numk[nb], ah, bhv);
                mma16816(numk[nb], ah, blv);
                mma16816(numk[nb], al, bhv);
            }
            {   // denominator block (cols 64-71; col 64 = norm)
                uint32_t bhv[2], blv[2];
                ldsm2t(bhv, sb + SM_PHI + (uint32_t)(ks * 16) * LDBB + 128 + btoff);
                ldsm2t(blv, sb + SM_PLO + (uint32_t)(ks * 16) * LDBB + 128 + btoff);
                mma16816(dk, ah, bhv);
                mma16816(dk, ah, blv);
                mma16816(dk, al, bhv);
            }
        }

        // ---- v' = values - numer_k/denom_k -> smem (bf16 split) -----------
        {
            float r0v = __frcp_rn(fmaxf(dk[0], EPSV));
            float r2v = __frcp_rn(fmaxf(dk[2], EPSV));
            float rka = __shfl_sync(0xffffffffu, r0v, srcl);
            float rkb = __shfl_sync(0xffffffffu, r2v, srcl);
            const int ra = R0 + g8, rb = ra + 8;
            const long long gra = baseg + (long long)(row0 + t0 + ra) * DE;
            const long long grb = baseg + (long long)(row0 + t0 + rb) * DE;
            #pragma unroll
            for (int nb = 0; nb < 8; nb++) {
                int col = nb * 8 + tig * 2;
                float2 va = *(const float2*)(values + gra + col);
                float2 vb = *(const float2*)(values + grb + col);
                float n0 = va.x - numk[nb][0] * rka;
                float n1 = va.y - numk[nb][1] * rka;
                float n2 = vb.x - numk[nb][2] * rkb;
                float n3 = vb.y - numk[nb][3] * rkb;
                float h0,l0,h1,l1,h2,l2,h3,l3;
                splitf(n0,h0,l0); splitf(n1,h1,l1);
                splitf(n2,h2,l2); splitf(n3,h3,l3);
                uint32_t oa = (uint32_t)ra * LDBB + col * 2;
                uint32_t ob = (uint32_t)rb * LDBB + col * 2;
                *(uint32_t*)(smc + SM_VHI + oa) = packbf(h0, h1);
                *(uint32_t*)(smc + SM_VLO + oa) = packbf(l0, l1);
                *(uint32_t*)(smc + SM_VHI + ob) = packbf(h2, h3);
                *(uint32_t*)(smc + SM_VLO + ob) = packbf(l2, l3);
            }
        }
        __syncthreads();

        // ============ GEMM2: new_kv += k^T v' ===============================
        #pragma unroll
        for (int ks = 0; ks < 8; ks++) {
            uint32_t ah[4], al[4];
            ldsm4t(ah, sb + SM_KHI + (uint32_t)(ks * 16) * LDBB + dR * 2 + atoff);
            ldsm4t(al, sb + SM_KLO + (uint32_t)(ks * 16) * LDBB + dR * 2 + atoff);
            #pragma unroll
            for (int nb = 0; nb < 4; nb++) {
                uint32_t bhv[2], blv[2];
                uint32_t bcol = (eoff + nb * 8) * 2;
                ldsm2t(bhv, sb + SM_VHI + (uint32_t)(ks * 16) * LDBB + bcol + btoff);
                ldsm2t(blv, sb + SM_VLO + (uint32_t)(ks * 16) * LDBB + bcol + btoff);
                mma16816(acc2[nb], ah, bhv);
                mma16816(acc2[nb], ah, blv);
                mma16816(acc2[nb], al, bhv);
            }
        }

        // ============ GEMM1-q: numer_q (2-term) + denom =====================
        #pragma unroll
        for (int i = 0; i < 8; i++)
            #pragma unroll
            for (int j = 0; j < 4; j++) numk[i][j] = 0.f;
        float dq[4] = {0.f, 0.f, 0.f, 0.f};
        #pragma unroll
        for (int ks = 0; ks < 4; ks++) {
            uint32_t aq[4];
            ldsm4(aq, sb + SM_QHI + (uint32_t)R0 * LDBB + ks * 32 + aoff);
            #pragma unroll
            for (int nb = 0; nb < 8; nb++) {
                uint32_t bhv[2], blv[2];
                ldsm2t(bhv, sb + SM_PHI + (uint32_t)(ks * 16) * LDBB + nb * 16 + btoff);
                ldsm2t(blv, sb + SM_PLO + (uint32_t)(ks * 16) * LDBB + nb * 16 + btoff);
                mma16816(numk[nb], aq, bhv);
                mma16816(numk[nb], aq, blv);
            }
            {
                uint32_t bhv[2], blv[2];
                ldsm2t(bhv, sb + SM_PHI + (uint32_t)(ks * 16) * LDBB + 128 + btoff);
                ldsm2t(blv, sb + SM_PLO + (uint32_t)(ks * 16) * LDBB + 128 + btoff);
                mma16816(dq, aq, bhv);
                mma16816(dq, aq, blv);
            }
        }

        // ---- out_g = out*gate + mem_out*(1-gate) -> global -----------------
        {
            float r0v = __frcp_rn(fmaxf(dq[0], EPSV));
            float r2v = __frcp_rn(fmaxf(dq[2], EPSV));
            float rqa = __shfl_sync(0xffffffffu, r0v, srcl) * gate1;
            float rqb = __shfl_sync(0xffffffffu, r2v, srcl) * gate1;
            const int ra = R0 + g8, rb = ra + 8;
            const long long gra = baseg + (long long)(row0 + t0 + ra) * DE;
            const long long grb = baseg + (long long)(row0 + t0 + rb) * DE;
            #pragma unroll
            for (int nb = 0; nb < 8; nb++) {
                int col = nb * 8 + tig * 2;
                float2 oa = *(const float2*)(outin + gra + col);
                float2 ob = *(const float2*)(outin + grb + col);
                float2 ga, gb;
                ga.x = oa.x * gate + numk[nb][0] * rqa;
                ga.y = oa.y * gate + numk[nb][1] * rqa;
                gb.x = ob.x * gate + numk[nb][2] * rqb;
                gb.y = ob.y * gate + numk[nb][3] * rqb;
                *(float2*)(dout + gra + col) = ga;
                *(float2*)(dout + grb + col) = gb;
            }
        }
        __syncthreads();
    }

    // ---- Epilogue: merge new_kv / new_norm ---------------------------------
    float* kvo = dout + KV_OFF + (long long)bh * DE * DE;
    #pragma unroll
    for (int nb = 0; nb < 4; nb++) {
        int col = eoff + nb * 8 + tig * 2;
        atomicAdd(&kvo[(dR + g8) * DE + col],     acc2[nb][0]);
        atomicAdd(&kvo[(dR + g8) * DE + col + 1], acc2[nb][1]);
        atomicAdd(&kvo[(dR + g8 + 8) * DE + col],     acc2[nb][2]);
        atomicAdd(&kvo[(dR + g8 + 8) * DE + col + 1], acc2[nb][3]);
    }
    {
        float* no = dout + NORM_OFF + (long long)bh * DE;
        #pragma unroll
        for (int j = 0; j < 4; j++)
            atomicAdd(&no[4 * c15 + j], accn[j]);
    }
}

// ---------------------------------------------------------------------------
extern "C" void kernel_launch(void* const* d_in, const int* in_sizes, int n_in,
                              void* d_out, int out_size) {
    const float* keys    = (const float*)d_in[0];
    const float* values  = (const float*)d_in[1];
    const float* queries = (const float*)d_in[2];
    const float* outin   = (const float*)d_in[3];
    const float* pkv     = (const float*)d_in[4];
    const float* pnorm   = (const float*)d_in[5];
    const float* hg      = (const float*)d_in[6];
    float* dout = (float*)d_out;

    cudaFuncSetAttribute(fw_main, cudaFuncAttributeMaxDynamicSharedMemorySize,
                         SMEM_TOTAL);

    fw_init<<<(B_ * H_ * DE * DE + 255) / 256, 256>>>(pkv, pnorm, dout);

    dim3 grid(SPLIT, B_ * H_);
    fw_main<<<grid, 256, SMEM_TOTAL>>>(keys, values, queries, outin,
                                       pkv, pnorm, hg, dout);
}

// round 6
// speedup vs baseline: 1.9045x; 1.0654x over previous
#include <cuda_runtime.h>
#include <cuda_bf16.h>
#include <cstdint>

// Problem constants
#define B_    4
#define H_    16
#define N_    8192
#define DE    64
#define SPLIT 16
#define TM    128
#define EPSV  1e-10f

#define KV_OFF   ((long long)B_ * H_ * N_ * DE)
#define NORM_OFF (KV_OFF + (long long)B_ * H_ * DE * DE)

// bf16 tiles, row stride 72 elements (144 B)
#define LDB   72
#define LDBB  144
#define SM_KHI 0
#define SM_KLO 18432
#define SM_QHI 36864
#define SM_VHI 55296
#define SM_VLO 73728
#define SM_PHI 92160                 // pkv hi [64][72] (col 64 = norm)
#define SM_PLO (SM_PHI + 9216)
#define SMEM_TOTAL (SM_PLO + 9216)   // 110592 B -> 2 CTAs/SM

union F4 { float4 v; float a[4]; };

// ---------------------------------------------------------------------------
__device__ __forceinline__ uint32_t smem_u32(const void* p) {
    uint32_t a;
    asm("{ .reg .u64 t; cvta.to.shared.u64 t, %1; cvt.u32.u64 %0, t; }"
        : "=r"(a) : "l"(p));
    return a;
}
// NOTE: non-volatile (scheduler-friendly); "memory" clobber keeps ordering
// w.r.t. shared stores and barriers.
__device__ __forceinline__ void ldsm4(uint32_t* r, uint32_t addr) {
    asm("ldmatrix.sync.aligned.m8n8.x4.shared.b16 {%0,%1,%2,%3}, [%4];"
        : "=r"(r[0]), "=r"(r[1]), "=r"(r[2]), "=r"(r[3]) : "r"(addr) : "memory");
}
__device__ __forceinline__ void ldsm4t(uint32_t* r, uint32_t addr) {
    asm("ldmatrix.sync.aligned.m8n8.x4.trans.shared.b16 {%0,%1,%2,%3}, [%4];"
        : "=r"(r[0]), "=r"(r[1]), "=r"(r[2]), "=r"(r[3]) : "r"(addr) : "memory");
}
__device__ __forceinline__ void ldsm2t(uint32_t* r, uint32_t addr) {
    asm("ldmatrix.sync.aligned.m8n8.x2.trans.shared.b16 {%0,%1}, [%2];"
        : "=r"(r[0]), "=r"(r[1]) : "r"(addr) : "memory");
}
// Pure register op: fully schedulable.
__device__ __forceinline__ void mma16816(float* c, const uint32_t* a, const uint32_t* b) {
    asm("mma.sync.aligned.m16n8k16.row.col.f32.bf16.bf16.f32 "
        "{%0,%1,%2,%3}, {%4,%5,%6,%7}, {%8,%9}, {%0,%1,%2,%3};"
        : "+f"(c[0]), "+f"(c[1]), "+f"(c[2]), "+f"(c[3])
        : "r"(a[0]), "r"(a[1]), "r"(a[2]), "r"(a[3]), "r"(b[0]), "r"(b[1]));
}
__device__ __forceinline__ void pf_l2(const float* p) {
    asm("prefetch.global.L2 [%0];" :: "l"(p));
}

__device__ __forceinline__ float elu1(float x) {
    return x > 0.f ? x + 1.f : __expf(x);
}
__device__ __forceinline__ unsigned packbf(float x, float y) {
    __nv_bfloat162 t(__float2bfloat16(x), __float2bfloat16(y));
    return *reinterpret_cast<unsigned*>(&t);
}
__device__ __forceinline__ void splitf(float x, float& hi, float& lo) {
    hi = __bfloat162float(__float2bfloat16(x));
    lo = x - hi;
}

// ---------------------------------------------------------------------------
__global__ void fw_init(const float* __restrict__ pkv,
                        const float* __restrict__ pnorm,
                        float* __restrict__ dout) {
    int i = blockIdx.x * blockDim.x + threadIdx.x;
    if (i < B_ * H_ * DE * DE) dout[KV_OFF + i]   = pkv[i];
    if (i < B_ * H_ * DE)      dout[NORM_OFF + i] = pnorm[i];
}

// ---------------------------------------------------------------------------
__global__ __launch_bounds__(256, 2)
void fw_main(const float* __restrict__ keys,
             const float* __restrict__ values,
             const float* __restrict__ queries,
             const float* __restrict__ outin,
             const float* __restrict__ pkv,
             const float* __restrict__ pnorm,
             const float* __restrict__ hg,
             float* __restrict__ dout)
{
    extern __shared__ char smc[];
    const uint32_t sb = smem_u32(smc);

    const int tid  = threadIdx.x;
    const int lane = tid & 31;
    const int w    = tid >> 5;          // warp 0..7
    const int R0   = w * 16;            // row slice (GEMM1)
    const int split = blockIdx.x;
    const int bh    = blockIdx.y;
    const int h     = bh & (H_ - 1);

    const float gate  = 1.f / (1.f + __expf(-hg[h]));
    const float gate1 = 1.f - gate;

    // ---- stage pkv (hi/lo bf16) + norm column ------------------------------
    {
        const float* pg = pkv + (long long)bh * DE * DE;
        for (int i = tid; i < DE * DE; i += 256) {
            int d = i >> 6, e = i & 63;
            float hi, lo; splitf(pg[i], hi, lo);
            *(__nv_bfloat16*)(smc + SM_PHI + d * LDBB + e * 2) = __float2bfloat16(hi);
            *(__nv_bfloat16*)(smc + SM_PLO + d * LDBB + e * 2) = __float2bfloat16(lo);
        }
        const float* pn = pnorm + bh * DE;
        for (int i = tid; i < DE * 8; i += 256) {
            int d = i >> 3, c = 64 + (i & 7);
            float hi = 0.f, lo = 0.f;
            if (c == 64) splitf(pn[d], hi, lo);
            *(__nv_bfloat16*)(smc + SM_PHI + d * LDBB + c * 2) = __float2bfloat16(hi);
            *(__nv_bfloat16*)(smc + SM_PLO + d * LDBB + c * 2) = __float2bfloat16(lo);
        }
    }

    // ldmatrix per-lane offsets
    const uint32_t aoff  = (uint32_t)(lane & 15) * LDBB + ((lane & 16) ? 16 : 0);
    const uint32_t atoff = (uint32_t)((lane & 7) + ((lane & 16) ? 8 : 0)) * LDBB
                         + ((lane & 8) ? 16 : 0);
    const uint32_t btoff  = (uint32_t)(lane & 15) * LDBB;                   // x2
    const uint32_t btoff4 = (uint32_t)(lane & 15) * LDBB + ((lane & 16) ? 16 : 0); // x4 pair

    const int g8   = lane >> 2;
    const int tig  = lane & 3;
    const int srcl = (lane >> 2) << 2;

    // GEMM2 split: warps 0-3 / 4-7 share d-rows, cover e 0-31 / 32-63
    const int dR   = (w & 3) * 16;
    const int eoff = (w >> 2) * 32;

    float acc2[4][4];
    #pragma unroll
    for (int i = 0; i < 4; i++)
        #pragma unroll
        for (int j = 0; j < 4; j++) acc2[i][j] = 0.f;
    float accn[4] = {0.f, 0.f, 0.f, 0.f};

    const long long baseg = (long long)bh * N_ * DE;
    const int rows_per = N_ / SPLIT;    // 512
    const int row0 = split * rows_per;
    const int ntiles = rows_per / TM;   // 4
    const int c15 = tid & 15;

    for (int t = 0; t < ntiles; t++) {
        const int t0 = t * TM;

        // ============ Phase A: load k,q; elu; bf16-split to smem ============
        #pragma unroll
        for (int it = 0; it < 8; it++) {
            int row = (tid >> 4) + it * 16;
            long long g = baseg + (long long)(row0 + t0 + row) * DE + 4 * c15;
            F4 k4, q4;
            k4.v = *(const float4*)(keys + g);
            q4.v = *(const float4*)(queries + g);
            #pragma unroll
            for (int j = 0; j < 4; j++) { k4.a[j] = elu1(k4.a[j]); q4.a[j] = elu1(q4.a[j]); }
            #pragma unroll
            for (int j = 0; j < 4; j++) accn[j] += k4.a[j];

            float h0,l0,h1,l1,h2,l2,h3,l3;
            splitf(k4.a[0],h0,l0); splitf(k4.a[1],h1,l1);
            splitf(k4.a[2],h2,l2); splitf(k4.a[3],h3,l3);
            uint2 khi = make_uint2(packbf(h0,h1), packbf(h2,h3));
            uint2 klo = make_uint2(packbf(l0,l1), packbf(l2,l3));
            uint2 qhi = make_uint2(packbf(q4.a[0],q4.a[1]), packbf(q4.a[2],q4.a[3]));
            uint32_t off = (uint32_t)row * LDBB + 8 * c15;
            *(uint2*)(smc + SM_KHI + off) = khi;
            *(uint2*)(smc + SM_KLO + off) = klo;
            *(uint2*)(smc + SM_QHI + off) = qhi;
        }
        __syncthreads();

        // L2 prefetch of next tile (k,q,v) — free cover for tile-head latency
        if (t + 1 < ntiles) {
            long long gp = baseg + (long long)(row0 + t0 + TM + (tid >> 1)) * DE
                         + (tid & 1) * 32;
            pf_l2(keys + gp);
            pf_l2(queries + gp);
            pf_l2(values + gp);
        }

        // ============ GEMM1-k: numer_k (3-term) + denom (col 64) ============
        float numk[8][4];
        #pragma unroll
        for (int i = 0; i < 8; i++)
            #pragma unroll
            for (int j = 0; j < 4; j++) numk[i][j] = 0.f;
        float dk[4] = {0.f, 0.f, 0.f, 0.f};

        #pragma unroll
        for (int ks = 0; ks < 4; ks++) {
            uint32_t ah[4], al[4];
            ldsm4(ah, sb + SM_KHI + (uint32_t)R0 * LDBB + ks * 32 + aoff);
            ldsm4(al, sb + SM_KLO + (uint32_t)R0 * LDBB + ks * 32 + aoff);
            uint32_t bhf[4][4], blf[4][4];
            #pragma unroll
            for (int p = 0; p < 4; p++) {
                ldsm4t(bhf[p], sb + SM_PHI + (uint32_t)(ks * 16) * LDBB + p * 32 + btoff4);
                ldsm4t(blf[p], sb + SM_PLO + (uint32_t)(ks * 16) * LDBB + p * 32 + btoff4);
            }
            uint32_t dh[2], dl[2];
            ldsm2t(dh, sb + SM_PHI + (uint32_t)(ks * 16) * LDBB + 128 + btoff);
            ldsm2t(dl, sb + SM_PLO + (uint32_t)(ks * 16) * LDBB + 128 + btoff);
            #pragma unroll
            for (int p = 0; p < 4; p++) {
                mma16816(numk[2*p],   ah, bhf[p]);
                mma16816(numk[2*p],   ah, blf[p]);
                mma16816(numk[2*p],   al, bhf[p]);
                mma16816(numk[2*p+1], ah, bhf[p] + 2);
                mma16816(numk[2*p+1], ah, blf[p] + 2);
                mma16816(numk[2*p+1], al, bhf[p] + 2);
            }
            mma16816(dk, ah, dh);
            mma16816(dk, ah, dl);
            mma16816(dk, al, dh);
        }

        // ---- v' = values - numer_k/denom_k -> smem (bf16 split) -----------
        {
            float r0v = __frcp_rn(fmaxf(dk[0], EPSV));
            float r2v = __frcp_rn(fmaxf(dk[2], EPSV));
            float rka = __shfl_sync(0xffffffffu, r0v, srcl);
            float rkb = __shfl_sync(0xffffffffu, r2v, srcl);
            const int ra = R0 + g8, rb = ra + 8;
            const long long gra = baseg + (long long)(row0 + t0 + ra) * DE;
            const long long grb = baseg + (long long)(row0 + t0 + rb) * DE;
            #pragma unroll
            for (int nb = 0; nb < 8; nb++) {
                int col = nb * 8 + tig * 2;
                float2 va = *(const float2*)(values + gra + col);
                float2 vb = *(const float2*)(values + grb + col);
                float n0 = va.x - numk[nb][0] * rka;
                float n1 = va.y - numk[nb][1] * rka;
                float n2 = vb.x - numk[nb][2] * rkb;
                float n3 = vb.y - numk[nb][3] * rkb;
                float h0,l0,h1,l1,h2,l2,h3,l3;
                splitf(n0,h0,l0); splitf(n1,h1,l1);
                splitf(n2,h2,l2); splitf(n3,h3,l3);
                uint32_t oa = (uint32_t)ra * LDBB + col * 2;
                uint32_t ob = (uint32_t)rb * LDBB + col * 2;
                *(uint32_t*)(smc + SM_VHI + oa) = packbf(h0, h1);
                *(uint32_t*)(smc + SM_VLO + oa) = packbf(l0, l1);
                *(uint32_t*)(smc + SM_VHI + ob) = packbf(h2, h3);
                *(uint32_t*)(smc + SM_VLO + ob) = packbf(l2, l3);
            }
        }
        __syncthreads();

        // ============ GEMM2: new_kv += k^T v' (3-term) ======================
        #pragma unroll
        for (int ks = 0; ks < 8; ks++) {
            uint32_t ah[4], al[4];
            ldsm4t(ah, sb + SM_KHI + (uint32_t)(ks * 16) * LDBB + dR * 2 + atoff);
            ldsm4t(al, sb + SM_KLO + (uint32_t)(ks * 16) * LDBB + dR * 2 + atoff);
            uint32_t bhf[2][4], blf[2][4];
            #pragma unroll
            for (int p = 0; p < 2; p++) {
                uint32_t bcol = (uint32_t)eoff * 2 + p * 32;
                ldsm4t(bhf[p], sb + SM_VHI + (uint32_t)(ks * 16) * LDBB + bcol + btoff4);
                ldsm4t(blf[p], sb + SM_VLO + (uint32_t)(ks * 16) * LDBB + bcol + btoff4);
            }
            #pragma unroll
            for (int p = 0; p < 2; p++) {
                mma16816(acc2[2*p],   ah, bhf[p]);
                mma16816(acc2[2*p],   ah, blf[p]);
                mma16816(acc2[2*p],   al, bhf[p]);
                mma16816(acc2[2*p+1], ah, bhf[p] + 2);
                mma16816(acc2[2*p+1], ah, blf[p] + 2);
                mma16816(acc2[2*p+1], al, bhf[p] + 2);
            }
        }

        // ============ GEMM1-q: numer_q (2-term) + denom =====================
        float numq[8][4];
        #pragma unroll
        for (int i = 0; i < 8; i++)
            #pragma unroll
            for (int j = 0; j < 4; j++) numq[i][j] = 0.f;
        float dq[4] = {0.f, 0.f, 0.f, 0.f};
        #pragma unroll
        for (int ks = 0; ks < 4; ks++) {
            uint32_t aq[4];
            ldsm4(aq, sb + SM_QHI + (uint32_t)R0 * LDBB + ks * 32 + aoff);
            uint32_t bhf[4][4], blf[4][4];
            #pragma unroll
            for (int p = 0; p < 4; p++) {
                ldsm4t(bhf[p], sb + SM_PHI + (uint32_t)(ks * 16) * LDBB + p * 32 + btoff4);
                ldsm4t(blf[p], sb + SM_PLO + (uint32_t)(ks * 16) * LDBB + p * 32 + btoff4);
            }
            uint32_t dh[2], dl[2];
            ldsm2t(dh, sb + SM_PHI + (uint32_t)(ks * 16) * LDBB + 128 + btoff);
            ldsm2t(dl, sb + SM_PLO + (uint32_t)(ks * 16) * LDBB + 128 + btoff);
            #pragma unroll
            for (int p = 0; p < 4; p++) {
                mma16816(numq[2*p],   aq, bhf[p]);
                mma16816(numq[2*p],   aq, blf[p]);
                mma16816(numq[2*p+1], aq, bhf[p] + 2);
                mma16816(numq[2*p+1], aq, blf[p] + 2);
            }
            mma16816(dq, aq, dh);
            mma16816(dq, aq, dl);
        }

        // ---- out_g = out*gate + mem_out*(1-gate) -> global -----------------
        {
            float r0v = __frcp_rn(fmaxf(dq[0], EPSV));
            float r2v = __frcp_rn(fmaxf(dq[2], EPSV));
            float rqa = __shfl_sync(0xffffffffu, r0v, srcl) * gate1;
            float rqb = __shfl_sync(0xffffffffu, r2v, srcl) * gate1;
            const int ra = R0 + g8, rb = ra + 8;
            const long long gra = baseg + (long long)(row0 + t0 + ra) * DE;
            const long long grb = baseg + (long long)(row0 + t0 + rb) * DE;
            #pragma unroll
            for (int nb = 0; nb < 8; nb++) {
                int col = nb * 8 + tig * 2;
                float2 oa = *(const float2*)(outin + gra + col);
                float2 ob = *(const float2*)(outin + grb + col);
                float2 ga, gb;
                ga.x = oa.x * gate + numq[nb][0] * rqa;
                ga.y = oa.y * gate + numq[nb][1] * rqa;
                gb.x = ob.x * gate + numq[nb][2] * rqb;
                gb.y = ob.y * gate + numq[nb][3] * rqb;
                *(float2*)(dout + gra + col) = ga;
                *(float2*)(dout + grb + col) = gb;
            }
        }
        __syncthreads();
    }

    // ---- Epilogue: merge new_kv / new_norm ---------------------------------
    float* kvo = dout + KV_OFF + (long long)bh * DE * DE;
    #pragma unroll
    for (int nb = 0; nb < 4; nb++) {
        int col = eoff + nb * 8 + tig * 2;
        atomicAdd(&kvo[(dR + g8) * DE + col],     acc2[nb][0]);
        atomicAdd(&kvo[(dR + g8) * DE + col + 1], acc2[nb][1]);
        atomicAdd(&kvo[(dR + g8 + 8) * DE + col],     acc2[nb][2]);
        atomicAdd(&kvo[(dR + g8 + 8) * DE + col + 1], acc2[nb][3]);
    }
    {
        float* no = dout + NORM_OFF + (long long)bh * DE;
        #pragma unroll
        for (int j = 0; j < 4; j++)
            atomicAdd(&no[4 * c15 + j], accn[j]);
    }
}

// ---------------------------------------------------------------------------
extern "C" void kernel_launch(void* const* d_in, const int* in_sizes, int n_in,
                              void* d_out, int out_size) {
    const float* keys    = (const float*)d_in[0];
    const float* values  = (const float*)d_in[1];
    const float* queries = (const float*)d_in[2];
    const float* outin   = (const float*)d_in[3];
    const float* pkv     = (const float*)d_in[4];
    const float* pnorm   = (const float*)d_in[5];
    const float* hg      = (const float*)d_in[6];
    float* dout = (float*)d_out;

    cudaFuncSetAttribute(fw_main, cudaFuncAttributeMaxDynamicSharedMemorySize,
                         SMEM_TOTAL);

    fw_init<<<(B_ * H_ * DE * DE + 255) / 256, 256>>>(pkv, pnorm, dout);

    dim3 grid(SPLIT, B_ * H_);
    fw_main<<<grid, 256, SMEM_TOTAL>>>(keys, values, queries, outin,
                                       pkv, pnorm, hg, dout);
}